// round 12
// baseline (speedup 1.0000x reference)
#include <cuda_runtime.h>
#include <math.h>

typedef unsigned long long u64;

#define T_DIM 2048
#define N_DIM 64
#define L_DIM 300
#define V_DIM 35
#define E_DIM 256
#define H_DIM 512
#define KS_DIM 128
#define VS_DIM 128

#define PRED_SIZE (N_DIM * L_DIM * V_DIM)
#define ATT_SIZE  (N_DIM * L_DIM * T_DIM)
#define NH (N_DIM * H_DIM)
#define NK (N_DIM * KS_DIM)

// ---- persistent device state (no allocations allowed) ----
#define S_H1  0
#define S_H2  (S_H1 + 2 * NH)
#define S_C1  (S_H2 + 2 * NH)
#define S_C2  (S_C1 + NH)
#define S_H3  (S_C2 + NH)
#define S_C3  (S_H3 + 2 * NK)
#define S_CTX (S_C3 + NK)
#define S_TOTAL (S_CTX + NK)

__device__ __align__(16) float g_state[S_TOTAL];
__device__ __align__(16) float g_emb[V_DIM * 2048];  // Wih1[:, :256]@emb[v] + bih1 + bhh1
__device__ int g_text[N_DIM * L_DIM];
__device__ int g_flag;

// grid barrier state
__device__ unsigned g_count;
__device__ volatile unsigned g_sense;

__device__ __forceinline__ u64 ffma2(u64 a, u64 b, u64 c) {
    u64 d;
    asm("fma.rn.f32x2 %0, %1, %2, %3;" : "=l"(d) : "l"(a), "l"(b), "l"(c));
    return d;
}
__device__ __forceinline__ float f2sum(u64 a) {
    float x, y;
    asm("mov.b64 {%0, %1}, %2;" : "=f"(x), "=f"(y) : "l"(a));
    return x + y;
}
__device__ __forceinline__ float4 ldcg4(const float* p) {
    return __ldcg((const float4*)p);
}

__device__ __forceinline__ void gbar(unsigned& lsense) {
    __syncthreads();
    if (threadIdx.x == 0) {
        lsense ^= 1u;
        __threadfence();
        if (atomicAdd(&g_count, 1u) == gridDim.x - 1) {
            g_count = 0;
            __threadfence();
            g_sense = lsense;
        } else {
            while (g_sense != lsense) __nanosleep(32);
        }
    }
    __syncthreads();
}

// ---------------- prologue kernels ----------------
__global__ void zero_kernel() {
    int i = blockIdx.x * blockDim.x + threadIdx.x;
    for (; i < S_TOTAL; i += gridDim.x * blockDim.x) g_state[i] = 0.f;
    if (blockIdx.x == 0 && threadIdx.x == 0) { g_flag = 0; g_count = 0; g_sense = 0; }
}
__global__ void detect_kernel(const int* __restrict__ t32) {
    int i = blockIdx.x * blockDim.x + threadIdx.x;
    int idx = 2 * i + 1;
    if (idx < N_DIM * L_DIM && t32[idx] != 0) atomicOr(&g_flag, 1);
}
__global__ void decode_kernel(const int* __restrict__ t32) {
    int i = blockIdx.x * blockDim.x + threadIdx.x;
    if (i < N_DIM * L_DIM) g_text[i] = g_flag ? t32[i] : t32[2 * i];
}
__global__ __launch_bounds__(256) void emb_kernel(
    const float* __restrict__ emb_W, const float* __restrict__ Wih1,
    const float* __restrict__ bih1, const float* __restrict__ bhh1)
{
    int r = blockIdx.x * 256 + threadIdx.x;
    int v = blockIdx.y;
    const float* w = Wih1 + (size_t)r * 384;
    const float* e = emb_W + (size_t)v * E_DIM;
    float acc = bih1[r] + bhh1[r];
#pragma unroll 8
    for (int k = 0; k < 256; ++k) acc += w[k] * e[k];
    g_emb[v * 2048 + r] = acc;
}

// ---------------- mm phases ----------------
// Layers 1 & 2: 128 blocks x 4 units. Thread (su=tid>>7, mid=(tid>>5)&3,
// b2=tid&31) computes ALL 4 gates of unit bid*4+su for batches b2 & b2+32,
// over the q-quarter [mid*8, mid*8+8) of each staged 128-k segment.
// x from smem feeds 16 ffma2 per 2 LDS.128 -> fma-bound.
template <int LAYER>
__device__ void mm12_phase(char* sbuf,
    const float* __restrict__ Wih, const float* __restrict__ Whh,
    const float* __restrict__ bih, const float* __restrict__ bhh,
    int l, int p, int bid, int tid)
{
    float4 (*s4)[65] = (float4(*)[65])sbuf;
    constexpr int NSEG = (LAYER == 1) ? 5 : 8;
    const bool act = bid < 128;
    const int su = tid >> 7;
    const int mid = (tid >> 5) & 3;
    const int b2 = tid & 31;
    const int j = bid * 4 + su;

    u64 acc[8];
#pragma unroll
    for (int i = 0; i < 8; ++i) acc[i] = 0ULL;

    for (int c = 0; c < NSEG; ++c) {
        __syncthreads();
        if (act) {
#pragma unroll
            for (int it = 0; it < 4; ++it) {
                int i4 = tid + it * 512;
                int bb = i4 >> 5, q = i4 & 31;
                const float* src;
                if (LAYER == 1)
                    src = (c == 0) ? g_state + S_CTX + bb * 128
                                   : g_state + S_H1 + p * NH + bb * 512 + (c - 1) * 128;
                else
                    src = (c < 4) ? g_state + S_H1 + (p ^ 1) * NH + bb * 512 + c * 128
                                  : g_state + S_H2 + p * NH + bb * 512 + (c - 4) * 128;
                s4[q][bb] = ldcg4(src + q * 4);
            }
        }
        __syncthreads();
        if (act) {
            const float* wbase;
            size_t rstr;
            int koff;
            if (LAYER == 1) {
                if (c == 0) { wbase = Wih; rstr = 384; koff = 256; }
                else        { wbase = Whh; rstr = 512; koff = (c - 1) * 128; }
            } else {
                if (c < 4) { wbase = Wih; rstr = 512; koff = c * 128; }
                else       { wbase = Whh; rstr = 512; koff = (c - 4) * 128; }
            }
            const ulonglong2* W0 = (const ulonglong2*)(wbase + (size_t)j * rstr + koff);
            const ulonglong2* W1 = (const ulonglong2*)(wbase + (size_t)(512 + j) * rstr + koff);
            const ulonglong2* W2 = (const ulonglong2*)(wbase + (size_t)(1024 + j) * rstr + koff);
            const ulonglong2* W3 = (const ulonglong2*)(wbase + (size_t)(1536 + j) * rstr + koff);
#pragma unroll
            for (int qi = 0; qi < 8; ++qi) {
                int q = mid * 8 + qi;
                ulonglong2 x0 = *(const ulonglong2*)&s4[q][b2];
                ulonglong2 x1 = *(const ulonglong2*)&s4[q][b2 + 32];
                ulonglong2 w0 = W0[q], w1 = W1[q], w2 = W2[q], w3 = W3[q];
                acc[0] = ffma2(w0.x, x0.x, acc[0]); acc[0] = ffma2(w0.y, x0.y, acc[0]);
                acc[1] = ffma2(w0.x, x1.x, acc[1]); acc[1] = ffma2(w0.y, x1.y, acc[1]);
                acc[2] = ffma2(w1.x, x0.x, acc[2]); acc[2] = ffma2(w1.y, x0.y, acc[2]);
                acc[3] = ffma2(w1.x, x1.x, acc[3]); acc[3] = ffma2(w1.y, x1.y, acc[3]);
                acc[4] = ffma2(w2.x, x0.x, acc[4]); acc[4] = ffma2(w2.y, x0.y, acc[4]);
                acc[5] = ffma2(w2.x, x1.x, acc[5]); acc[5] = ffma2(w2.y, x1.y, acc[5]);
                acc[6] = ffma2(w3.x, x0.x, acc[6]); acc[6] = ffma2(w3.y, x0.y, acc[6]);
                acc[7] = ffma2(w3.x, x1.x, acc[7]); acc[7] = ffma2(w3.y, x1.y, acc[7]);
            }
        }
    }
    __syncthreads();                     // s4 dead; overlay partial buffer
    float* s_part = (float*)sbuf;        // [su][g][mid][64]
    if (act) {
#pragma unroll
        for (int g = 0; g < 4; ++g) {
            s_part[((su * 4 + g) * 4 + mid) * 64 + b2]      = f2sum(acc[g * 2]);
            s_part[((su * 4 + g) * 4 + mid) * 64 + b2 + 32] = f2sum(acc[g * 2 + 1]);
        }
    }
    __syncthreads();
    if (act && tid < 256) {
        int fu = tid >> 6, b = tid & 63;
        int fj = bid * 4 + fu;
        float s[4];
#pragma unroll
        for (int g = 0; g < 4; ++g) {
            const float* pp = s_part + ((fu * 4 + g) * 4) * 64 + b;
            s[g] = pp[0] + pp[64] + pp[128] + pp[192];
        }
        if (LAYER == 1) {
            int tok = g_text[b * L_DIM + l];
            const float* e = g_emb + tok * 2048;
            s[0] += e[fj]; s[1] += e[512 + fj]; s[2] += e[1024 + fj]; s[3] += e[1536 + fj];
        } else {
            s[0] += bih[fj] + bhh[fj];
            s[1] += bih[512 + fj] + bhh[512 + fj];
            s[2] += bih[1024 + fj] + bhh[1024 + fj];
            s[3] += bih[1536 + fj] + bhh[1536 + fj];
        }
        float ig = 1.f / (1.f + expf(-s[0]));
        float fg = 1.f / (1.f + expf(-s[1]));
        float gg = tanhf(s[2]);
        float og = 1.f / (1.f + expf(-s[3]));
        float* cb = g_state + ((LAYER == 1) ? S_C1 : S_C2) + b * 512 + fj;
        float cn = fg * __ldcg(cb) + ig * gg;
        *cb = cn;
        g_state[((LAYER == 1) ? S_H1 : S_H2) + (p ^ 1) * NH + b * 512 + fj] = og * tanhf(cn);
    }
}

// Layer 3: 128 blocks x 1 unit (j = bid). Thread (mid = tid>>6 in 0..7, b = tid&63),
// all 4 gates, q-eighth [mid*4, mid*4+4) of each segment.
__device__ void mm3_phase(char* sbuf,
    const float* __restrict__ Wih3, const float* __restrict__ Whh3,
    const float* __restrict__ bih3, const float* __restrict__ bhh3,
    int p, int bid, int tid)
{
    float4 (*s4)[65] = (float4(*)[65])sbuf;
    const bool act = bid < 128;
    const int mid = tid >> 6;
    const int b = tid & 63;
    const int j = bid;

    u64 acc[4];
#pragma unroll
    for (int i = 0; i < 4; ++i) acc[i] = 0ULL;

    for (int c = 0; c < 5; ++c) {
        __syncthreads();
        if (act) {
#pragma unroll
            for (int it = 0; it < 4; ++it) {
                int i4 = tid + it * 512;
                int bb = i4 >> 5, q = i4 & 31;
                const float* src = (c < 4)
                    ? g_state + S_H2 + (p ^ 1) * NH + bb * 512 + c * 128
                    : g_state + S_H3 + p * NK + bb * 128;
                s4[q][bb] = ldcg4(src + q * 4);
            }
        }
        __syncthreads();
        if (act) {
            const float* wbase = (c < 4) ? Wih3 : Whh3;
            size_t rstr = (c < 4) ? 512 : 128;
            int koff = (c < 4) ? c * 128 : 0;
            const ulonglong2* W0 = (const ulonglong2*)(wbase + (size_t)j * rstr + koff);
            const ulonglong2* W1 = (const ulonglong2*)(wbase + (size_t)(128 + j) * rstr + koff);
            const ulonglong2* W2 = (const ulonglong2*)(wbase + (size_t)(256 + j) * rstr + koff);
            const ulonglong2* W3 = (const ulonglong2*)(wbase + (size_t)(384 + j) * rstr + koff);
#pragma unroll
            for (int qi = 0; qi < 4; ++qi) {
                int q = mid * 4 + qi;
                ulonglong2 xv = *(const ulonglong2*)&s4[q][b];
                ulonglong2 w0 = W0[q], w1 = W1[q], w2 = W2[q], w3 = W3[q];
                acc[0] = ffma2(w0.x, xv.x, acc[0]); acc[0] = ffma2(w0.y, xv.y, acc[0]);
                acc[1] = ffma2(w1.x, xv.x, acc[1]); acc[1] = ffma2(w1.y, xv.y, acc[1]);
                acc[2] = ffma2(w2.x, xv.x, acc[2]); acc[2] = ffma2(w2.y, xv.y, acc[2]);
                acc[3] = ffma2(w3.x, xv.x, acc[3]); acc[3] = ffma2(w3.y, xv.y, acc[3]);
            }
        }
    }
    __syncthreads();
    float* s_part = (float*)sbuf;   // [g][mid][64]
    if (act) {
#pragma unroll
        for (int g = 0; g < 4; ++g)
            s_part[(g * 8 + mid) * 64 + b] = f2sum(acc[g]);
    }
    __syncthreads();
    if (act && tid < 64) {
        int fb = tid;
        float s[4];
#pragma unroll
        for (int g = 0; g < 4; ++g) {
            float a = 0.f;
#pragma unroll
            for (int m = 0; m < 8; ++m) a += s_part[(g * 8 + m) * 64 + fb];
            s[g] = a;
        }
        s[0] += bih3[j] + bhh3[j];
        s[1] += bih3[128 + j] + bhh3[128 + j];
        s[2] += bih3[256 + j] + bhh3[256 + j];
        s[3] += bih3[384 + j] + bhh3[384 + j];
        float ig = 1.f / (1.f + expf(-s[0]));
        float fg = 1.f / (1.f + expf(-s[1]));
        float gg = tanhf(s[2]);
        float og = 1.f / (1.f + expf(-s[3]));
        float* cb = g_state + S_C3 + fb * 128 + j;
        float cn = fg * __ldcg(cb) + ig * gg;
        *cb = cn;
        g_state[S_H3 + (p ^ 1) * NK + fb * 128 + j] = og * tanhf(cn);
    }
}

// ---------------- attention + logits, one block per batch ----------------
// lane-per-t energy (no shuffles): each thread streams its own 512B key row,
// h3 broadcast from smem; then block softmax, att write, ctx, logits.
__device__ void attn_phase(char* sbuf, float* s_red, float* s_h3, float* s_ctx,
    const float* __restrict__ key, const float* __restrict__ values,
    const int* __restrict__ x_lens,
    const float* __restrict__ emb_W, const float* __restrict__ b_out,
    float* __restrict__ out, int l, int p, int write_att, int bid, int tid)
{
    if (bid >= 64) return;
    float* s_e = (float*)sbuf;   // 2048 floats
    const int n = bid;
    const int w = tid >> 5, lane = tid & 31;

    if (tid < 128) s_h3[tid] = __ldcg(g_state + S_H3 + (p ^ 1) * NK + n * 128 + tid);
    __syncthreads();

    const int len = __ldg(x_lens + n);
    const ulonglong2* h2p = (const ulonglong2*)s_h3;

    // energy: t = tid + 512*pass, full k in-register accumulation
#pragma unroll
    for (int pass = 0; pass < 4; ++pass) {
        int t = pass * 512 + tid;
        if (t < len) {
            const ulonglong2* kr = (const ulonglong2*)(key + ((size_t)t * N_DIM + n) * KS_DIM);
            u64 a0 = 0, a1 = 0, a2 = 0, a3 = 0;
#pragma unroll
            for (int c = 0; c < 16; ++c) {
                ulonglong2 k0 = __ldcs(kr + 2 * c);
                ulonglong2 k1 = __ldcs(kr + 2 * c + 1);
                ulonglong2 h0 = h2p[2 * c];
                ulonglong2 h1 = h2p[2 * c + 1];
                a0 = ffma2(k0.x, h0.x, a0);
                a1 = ffma2(k0.y, h0.y, a1);
                a2 = ffma2(k1.x, h1.x, a2);
                a3 = ffma2(k1.y, h1.y, a3);
            }
            s_e[t] = f2sum(a0) + f2sum(a1) + f2sum(a2) + f2sum(a3);
        } else {
            s_e[t] = -1e9f;
        }
    }
    __syncthreads();

    // block max
    float m = fmaxf(fmaxf(s_e[tid], s_e[tid + 512]),
                    fmaxf(s_e[tid + 1024], s_e[tid + 1536]));
    s_red[tid] = m; __syncthreads();
#pragma unroll
    for (int off = 256; off > 0; off >>= 1) {
        if (tid < off) s_red[tid] = fmaxf(s_red[tid], s_red[tid + off]);
        __syncthreads();
    }
    m = s_red[0];
    __syncthreads();

    // exp + block sum
    float sm = 0.f;
#pragma unroll
    for (int pass = 0; pass < 4; ++pass) {
        int t = pass * 512 + tid;
        float pv = expf(s_e[t] - m);
        s_e[t] = pv;
        sm += pv;
    }
    s_red[tid] = sm; __syncthreads();
#pragma unroll
    for (int off = 256; off > 0; off >>= 1) {
        if (tid < off) s_red[tid] += s_red[tid + off];
        __syncthreads();
    }
    float inv = 1.f / s_red[0];
    __syncthreads();

    float* att = out + PRED_SIZE + ((size_t)n * L_DIM + l) * T_DIM;
#pragma unroll
    for (int pass = 0; pass < 4; ++pass) {
        int t = pass * 512 + tid;
        float a = s_e[t] * inv;
        s_e[t] = a;
        if (write_att) att[t] = a;
    }
    __syncthreads();

    // context: (e = tid&127, tg = tid>>7), 4-way t split; p==0 beyond len
    {
        int e = tid & 127, tg = tid >> 7;
        float acc = 0.f;
#pragma unroll 4
        for (int t = tg; t < len; t += 4)
            acc += s_e[t] * __ldcs(values + ((size_t)t * N_DIM + n) * VS_DIM + e);
        s_red[tid] = acc;
        __syncthreads();
        if (tid < 128) {
            float cx = s_red[tid] + s_red[128 + tid] + s_red[256 + tid] + s_red[384 + tid];
            s_ctx[tid] = cx;
            g_state[S_CTX + n * 128 + tid] = cx;
        }
    }
    __syncthreads();

    // logits: 35 rows, K = 256 = [h3 || ctx]
    for (int r = w; r < V_DIM; r += 16) {
        const float* er = emb_W + (size_t)r * E_DIM;
        float4 w1 = *(const float4*)(er + lane * 4);
        float4 w2 = *(const float4*)(er + 128 + lane * 4);
        float4 x1 = *(const float4*)(s_h3 + lane * 4);
        float4 x2 = *(const float4*)(s_ctx + lane * 4);
        float sum = w1.x * x1.x + w1.y * x1.y + w1.z * x1.z + w1.w * x1.w
                  + w2.x * x2.x + w2.y * x2.y + w2.z * x2.z + w2.w * x2.w;
#pragma unroll
        for (int o = 16; o > 0; o >>= 1) sum += __shfl_xor_sync(0xffffffffu, sum, o);
        if (lane == 0) out[((size_t)n * L_DIM + l) * V_DIM + r] = sum + b_out[r];
    }
}

// ---------------- the persistent kernel ----------------
__global__ __launch_bounds__(512) void decoder_kernel(
    const float* __restrict__ key, const float* __restrict__ values,
    const int* __restrict__ x_lens,
    const float* __restrict__ emb_W,
    const float* __restrict__ Wih1, const float* __restrict__ Whh1,
    const float* __restrict__ Wih2, const float* __restrict__ Whh2,
    const float* __restrict__ bih2, const float* __restrict__ bhh2,
    const float* __restrict__ Wih3, const float* __restrict__ Whh3,
    const float* __restrict__ bih3, const float* __restrict__ bhh3,
    const float* __restrict__ b_out,
    float* __restrict__ out, int write_att)
{
    __shared__ __align__(16) char sbuf[32 * 65 * 16];  // x-slab / partials / s_e union
    __shared__ float s_red[512];
    __shared__ __align__(16) float s_h3[128];
    __shared__ __align__(16) float s_ctx[128];

    const int bid = blockIdx.x;
    const int tid = threadIdx.x;
    unsigned lsense = 0;

#pragma unroll 1
    for (int l = 0; l < L_DIM; ++l) {
        const int p = l & 1;
        mm12_phase<1>(sbuf, Wih1, Whh1, (const float*)0, (const float*)0, l, p, bid, tid);
        gbar(lsense);
        mm12_phase<2>(sbuf, Wih2, Whh2, bih2, bhh2, l, p, bid, tid);
        gbar(lsense);
        mm3_phase(sbuf, Wih3, Whh3, bih3, bhh3, p, bid, tid);
        gbar(lsense);
        attn_phase(sbuf, s_red, s_h3, s_ctx, key, values, x_lens,
                   emb_W, b_out, out, l, p, write_att, bid, tid);
        gbar(lsense);
    }
}

extern "C" void kernel_launch(void* const* d_in, const int* in_sizes, int n_in,
                              void* d_out, int out_size) {
    const float* key    = (const float*)d_in[0];
    const float* values = (const float*)d_in[1];
    const int*   x_lens = (const int*)d_in[2];
    const int*   text32 = (const int*)d_in[3];
    const float* emb_W  = (const float*)d_in[4];
    const float* Wih1 = (const float*)d_in[5];
    const float* Whh1 = (const float*)d_in[6];
    const float* bih1 = (const float*)d_in[7];
    const float* bhh1 = (const float*)d_in[8];
    const float* Wih2 = (const float*)d_in[9];
    const float* Whh2 = (const float*)d_in[10];
    const float* bih2 = (const float*)d_in[11];
    const float* bhh2 = (const float*)d_in[12];
    const float* Wih3 = (const float*)d_in[13];
    const float* Whh3 = (const float*)d_in[14];
    const float* bih3 = (const float*)d_in[15];
    const float* bhh3 = (const float*)d_in[16];
    const float* b_out = (const float*)d_in[17];
    float* out = (float*)d_out;

    int write_att = (out_size >= PRED_SIZE + ATT_SIZE) ? 1 : 0;

    int dev = 0, nsm = 148;
    cudaGetDevice(&dev);
    cudaDeviceGetAttribute(&nsm, cudaDevAttrMultiProcessorCount, dev);
    if (nsm < 128) nsm = 128;   // phase mappings need >=128 co-resident blocks

    zero_kernel<<<216, 256>>>();
    detect_kernel<<<(N_DIM * L_DIM / 2 + 255) / 256, 256>>>(text32);
    decode_kernel<<<(N_DIM * L_DIM + 255) / 256, 256>>>(text32);
    emb_kernel<<<dim3(8, V_DIM), 256>>>(emb_W, Wih1, bih1, bhh1);

    decoder_kernel<<<nsm, 512>>>(key, values, x_lens, emb_W,
                                 Wih1, Whh1, Wih2, Whh2, bih2, bhh2,
                                 Wih3, Whh3, bih3, bhh3, b_out,
                                 out, write_att);
}

// round 16
// speedup vs baseline: 1.6518x; 1.6518x over previous
#include <cuda_runtime.h>
#include <math.h>

typedef unsigned long long u64;

#define T_DIM 2048
#define N_DIM 64
#define L_DIM 300
#define V_DIM 35
#define E_DIM 256
#define H_DIM 512
#define KS_DIM 128
#define VS_DIM 128

#define PRED_SIZE (N_DIM * L_DIM * V_DIM)
#define ATT_SIZE  (N_DIM * L_DIM * T_DIM)
#define NH (N_DIM * H_DIM)
#define NK (N_DIM * KS_DIM)

// ---- persistent device state (no allocations allowed) ----
#define S_H1  0
#define S_H2  (S_H1 + 2 * NH)
#define S_C1  (S_H2 + 2 * NH)
#define S_C2  (S_C1 + NH)
#define S_H3  (S_C2 + NH)
#define S_C3  (S_H3 + 2 * NK)
#define S_TOTAL (S_C3 + NK)

__device__ __align__(16) float g_state[S_TOTAL];
__device__ __align__(16) float g_emb[V_DIM * 2048];  // Wih1[:, :256]@emb[v] + bih1 + bhh1
__device__ __align__(16) float g_pw[N_DIM * T_DIM];  // unnormalized softmax numerators
__device__ __align__(16) float g_cw[N_DIM * 4 * KS_DIM];  // per-slice partial ctx
__device__ float g_ms[N_DIM * 4];
__device__ float g_ls[N_DIM * 4];
__device__ int g_text[N_DIM * L_DIM];
__device__ int g_flag;

__device__ unsigned g_count;
__device__ volatile unsigned g_sense;

__device__ __forceinline__ u64 ffma2(u64 a, u64 b, u64 c) {
    u64 d;
    asm("fma.rn.f32x2 %0, %1, %2, %3;" : "=l"(d) : "l"(a), "l"(b), "l"(c));
    return d;
}
__device__ __forceinline__ float f2sum(u64 a) {
    float x, y;
    asm("mov.b64 {%0, %1}, %2;" : "=f"(x), "=f"(y) : "l"(a));
    return x + y;
}
__device__ __forceinline__ float4 ldcg4(const float* p) {
    return __ldcg((const float4*)p);
}

__device__ __forceinline__ void gbar(unsigned& lsense) {
    __syncthreads();
    if (threadIdx.x == 0) {
        lsense ^= 1u;
        __threadfence();
        if (atomicAdd(&g_count, 1u) == gridDim.x - 1) {
            g_count = 0;
            __threadfence();
            g_sense = lsense;
        } else {
            while (g_sense != lsense) __nanosleep(32);
        }
    }
    __syncthreads();
}

// ---------------- prologue kernels ----------------
__global__ void zero_kernel() {
    int i = blockIdx.x * blockDim.x + threadIdx.x;
    for (; i < S_TOTAL; i += gridDim.x * blockDim.x) g_state[i] = 0.f;
    if (blockIdx.x == 0 && threadIdx.x == 0) { g_flag = 0; g_count = 0; g_sense = 0; }
}
__global__ void detect_kernel(const int* __restrict__ t32) {
    int i = blockIdx.x * blockDim.x + threadIdx.x;
    int idx = 2 * i + 1;
    if (idx < N_DIM * L_DIM && t32[idx] != 0) atomicOr(&g_flag, 1);
}
__global__ void decode_kernel(const int* __restrict__ t32) {
    int i = blockIdx.x * blockDim.x + threadIdx.x;
    if (i < N_DIM * L_DIM) g_text[i] = g_flag ? t32[i] : t32[2 * i];
}
__global__ __launch_bounds__(256) void emb_kernel(
    const float* __restrict__ emb_W, const float* __restrict__ Wih1,
    const float* __restrict__ bih1, const float* __restrict__ bhh1)
{
    int r = blockIdx.x * 256 + threadIdx.x;
    int v = blockIdx.y;
    const float* w = Wih1 + (size_t)r * 384;
    const float* e = emb_W + (size_t)v * E_DIM;
    float acc = bih1[r] + bhh1[r];
#pragma unroll 8
    for (int k = 0; k < 256; ++k) acc += w[k] * e[k];
    g_emb[v * 2048 + r] = acc;
}

// ---------------- mm phases (R8 structure) ----------------
// 128 blocks x 4 units; thread (su=tid>>7, g=(tid>>5)&3, b2=tid&31) computes
// gate row g*512 + bid*4+su for batches b2, b2+32 over full K.
// Layer 1, segment 0 = ctx, combined inline from attention slice partials.
template <int LAYER>
__device__ void mm12_phase(char* sbuf, float (*s_fin)[4][64], float* s_scale,
    const float* __restrict__ Wih, const float* __restrict__ Whh,
    const float* __restrict__ bih, const float* __restrict__ bhh,
    int l, int p, int bid, int tid)
{
    float4 (*s4)[65] = (float4(*)[65])sbuf;
    constexpr int NSEG = (LAYER == 1) ? 5 : 8;
    const int su = tid >> 7;
    const int g = (tid >> 5) & 3;
    const int b2 = tid & 31;
    const int j = bid * 4 + su;
    const int r = g * 512 + j;

    if (LAYER == 1) {
        if (tid < 64 && l > 0) {
            int n = tid;
            float m0 = __ldcg(g_ms + n * 4 + 0), m1 = __ldcg(g_ms + n * 4 + 1);
            float m2 = __ldcg(g_ms + n * 4 + 2), m3 = __ldcg(g_ms + n * 4 + 3);
            float M = fmaxf(fmaxf(m0, m1), fmaxf(m2, m3));
            float e0 = expf(m0 - M), e1 = expf(m1 - M);
            float e2 = expf(m2 - M), e3 = expf(m3 - M);
            float Z = __ldcg(g_ls + n * 4 + 0) * e0 + __ldcg(g_ls + n * 4 + 1) * e1
                    + __ldcg(g_ls + n * 4 + 2) * e2 + __ldcg(g_ls + n * 4 + 3) * e3;
            float iz = 1.f / Z;
            s_scale[n * 4 + 0] = e0 * iz; s_scale[n * 4 + 1] = e1 * iz;
            s_scale[n * 4 + 2] = e2 * iz; s_scale[n * 4 + 3] = e3 * iz;
        }
    }

    u64 a0 = 0, a1 = 0, c0 = 0, c1 = 0;
    for (int c = 0; c < NSEG; ++c) {
        __syncthreads();
#pragma unroll
        for (int it = 0; it < 4; ++it) {
            int i4 = tid + it * 512;
            int bb = i4 >> 5, q = i4 & 31;
            float4 v;
            if (LAYER == 1 && c == 0) {
                if (l > 0) {
                    const float4* cwp = (const float4*)(g_cw + bb * 4 * 128);
                    float4 w0 = __ldcg(cwp + q);
                    float4 w1 = __ldcg(cwp + 32 + q);
                    float4 w2 = __ldcg(cwp + 64 + q);
                    float4 w3 = __ldcg(cwp + 96 + q);
                    float sc0 = s_scale[bb * 4 + 0], sc1 = s_scale[bb * 4 + 1];
                    float sc2 = s_scale[bb * 4 + 2], sc3 = s_scale[bb * 4 + 3];
                    v = make_float4(w0.x * sc0 + w1.x * sc1 + w2.x * sc2 + w3.x * sc3,
                                    w0.y * sc0 + w1.y * sc1 + w2.y * sc2 + w3.y * sc3,
                                    w0.z * sc0 + w1.z * sc1 + w2.z * sc2 + w3.z * sc3,
                                    w0.w * sc0 + w1.w * sc1 + w2.w * sc2 + w3.w * sc3);
                } else {
                    v = make_float4(0.f, 0.f, 0.f, 0.f);
                }
            } else if (LAYER == 1) {
                v = ldcg4(g_state + S_H1 + p * NH + bb * 512 + (c - 1) * 128 + q * 4);
            } else {
                const float* src = (c < 4)
                    ? g_state + S_H1 + (p ^ 1) * NH + bb * 512 + c * 128
                    : g_state + S_H2 + p * NH + bb * 512 + (c - 4) * 128;
                v = ldcg4(src + q * 4);
            }
            s4[q][bb] = v;
        }
        __syncthreads();
        const float* wbase;
        size_t rstr;
        int koff;
        if (LAYER == 1) {
            if (c == 0) { wbase = Wih; rstr = 384; koff = 256; }
            else        { wbase = Whh; rstr = 512; koff = (c - 1) * 128; }
        } else {
            if (c < 4) { wbase = Wih; rstr = 512; koff = c * 128; }
            else       { wbase = Whh; rstr = 512; koff = (c - 4) * 128; }
        }
        const ulonglong2* W = (const ulonglong2*)(wbase + (size_t)r * rstr + koff);
#pragma unroll
        for (int q = 0; q < 32; ++q) {
            ulonglong2 wv = W[q];
            ulonglong2 x0 = *(const ulonglong2*)&s4[q][b2];
            ulonglong2 x1 = *(const ulonglong2*)&s4[q][b2 + 32];
            a0 = ffma2(wv.x, x0.x, a0); a1 = ffma2(wv.y, x0.y, a1);
            c0 = ffma2(wv.x, x1.x, c0); c1 = ffma2(wv.y, x1.y, c1);
        }
    }
    s_fin[su][g][b2]      = f2sum(a0) + f2sum(a1);
    s_fin[su][g][b2 + 32] = f2sum(c0) + f2sum(c1);
    __syncthreads();
    if (tid < 256) {
        int fu = tid >> 6, b = tid & 63;
        int fj = bid * 4 + fu;
        float s0 = s_fin[fu][0][b], s1 = s_fin[fu][1][b];
        float s2 = s_fin[fu][2][b], s3 = s_fin[fu][3][b];
        if (LAYER == 1) {
            int tok = g_text[b * L_DIM + l];
            const float* e = g_emb + tok * 2048;
            s0 += e[fj]; s1 += e[512 + fj]; s2 += e[1024 + fj]; s3 += e[1536 + fj];
        } else {
            s0 += bih[fj] + bhh[fj];
            s1 += bih[512 + fj] + bhh[512 + fj];
            s2 += bih[1024 + fj] + bhh[1024 + fj];
            s3 += bih[1536 + fj] + bhh[1536 + fj];
        }
        float ig = 1.f / (1.f + expf(-s0));
        float fg = 1.f / (1.f + expf(-s1));
        float gg = tanhf(s2);
        float og = 1.f / (1.f + expf(-s3));
        float* cb = g_state + ((LAYER == 1) ? S_C1 : S_C2) + b * 512 + fj;
        float cn = fg * (*cb) + ig * gg;
        *cb = cn;
        g_state[((LAYER == 1) ? S_H1 : S_H2) + (p ^ 1) * NH + b * 512 + fj] = og * tanhf(cn);
    }
}

// Layer 3: 128 blocks x 1 unit (j = bid); thread (mid=tid>>6 in 0..7, b=tid&63),
// all 4 gates, q-eighth of each segment; partials combined in smem.
__device__ void mm3_phase(char* sbuf,
    const float* __restrict__ Wih3, const float* __restrict__ Whh3,
    const float* __restrict__ bih3, const float* __restrict__ bhh3,
    int p, int bid, int tid)
{
    float4 (*s4)[65] = (float4(*)[65])sbuf;
    const int mid = tid >> 6;
    const int b = tid & 63;
    const int j = bid;

    u64 acc[4];
#pragma unroll
    for (int i = 0; i < 4; ++i) acc[i] = 0ULL;

    for (int c = 0; c < 5; ++c) {
        __syncthreads();
#pragma unroll
        for (int it = 0; it < 4; ++it) {
            int i4 = tid + it * 512;
            int bb = i4 >> 5, q = i4 & 31;
            const float* src = (c < 4)
                ? g_state + S_H2 + (p ^ 1) * NH + bb * 512 + c * 128
                : g_state + S_H3 + p * NK + bb * 128;
            s4[q][bb] = ldcg4(src + q * 4);
        }
        __syncthreads();
        const float* wbase = (c < 4) ? Wih3 : Whh3;
        size_t rstr = (c < 4) ? 512 : 128;
        int koff = (c < 4) ? c * 128 : 0;
        const ulonglong2* W0 = (const ulonglong2*)(wbase + (size_t)j * rstr + koff);
        const ulonglong2* W1 = (const ulonglong2*)(wbase + (size_t)(128 + j) * rstr + koff);
        const ulonglong2* W2 = (const ulonglong2*)(wbase + (size_t)(256 + j) * rstr + koff);
        const ulonglong2* W3 = (const ulonglong2*)(wbase + (size_t)(384 + j) * rstr + koff);
#pragma unroll
        for (int qi = 0; qi < 4; ++qi) {
            int q = mid * 4 + qi;
            ulonglong2 xv = *(const ulonglong2*)&s4[q][b];
            ulonglong2 w0 = W0[q], w1 = W1[q], w2 = W2[q], w3 = W3[q];
            acc[0] = ffma2(w0.x, xv.x, acc[0]); acc[0] = ffma2(w0.y, xv.y, acc[0]);
            acc[1] = ffma2(w1.x, xv.x, acc[1]); acc[1] = ffma2(w1.y, xv.y, acc[1]);
            acc[2] = ffma2(w2.x, xv.x, acc[2]); acc[2] = ffma2(w2.y, xv.y, acc[2]);
            acc[3] = ffma2(w3.x, xv.x, acc[3]); acc[3] = ffma2(w3.y, xv.y, acc[3]);
        }
    }
    __syncthreads();
    float* s_part = (float*)sbuf;   // [g][mid][64]
#pragma unroll
    for (int g = 0; g < 4; ++g)
        s_part[(g * 8 + mid) * 64 + b] = f2sum(acc[g]);
    __syncthreads();
    if (tid < 64) {
        int fb = tid;
        float s[4];
#pragma unroll
        for (int g = 0; g < 4; ++g) {
            float a = 0.f;
#pragma unroll
            for (int m = 0; m < 8; ++m) a += s_part[(g * 8 + m) * 64 + fb];
            s[g] = a;
        }
        s[0] += bih3[j] + bhh3[j];
        s[1] += bih3[128 + j] + bhh3[128 + j];
        s[2] += bih3[256 + j] + bhh3[256 + j];
        s[3] += bih3[384 + j] + bhh3[384 + j];
        float ig = 1.f / (1.f + expf(-s[0]));
        float fg = 1.f / (1.f + expf(-s[1]));
        float gg = tanhf(s[2]);
        float og = 1.f / (1.f + expf(-s[3]));
        float* cb = g_state + S_C3 + fb * 128 + j;
        float cn = fg * (*cb) + ig * gg;
        *cb = cn;
        g_state[S_H3 + (p ^ 1) * NK + fb * 128 + j] = og * tanhf(cn);
    }
}

// -------- attention slices: 256 tasks (4 slices x 64 n) over all blocks --------
// warp-per-t coalesced energy (unroll 2), thread-per-t softmax stats,
// float4-lane ctx partials. Writes g_pw, g_ms, g_ls, g_cw.
__device__ void attn_phase(char* sbuf, float* s_h3,
    const float* __restrict__ key, const float* __restrict__ values,
    const int* __restrict__ x_lens, int p, int bid, int tid)
{
    float* s_e = (float*)sbuf;                 // 512 floats
    float* s_red = (float*)(sbuf + 2048);      // 512 floats (overlaps red4 in time)
    float4* red4 = (float4*)(sbuf + 2048);     // 512 float4
    const int w = tid >> 5, lane = tid & 31;

    for (int tk = bid; tk < 256; tk += gridDim.x) {
        const int n = tk & 63, s = tk >> 6;
        const int t0 = s * 512;
        __syncthreads();
        if (tid < 128) s_h3[tid] = __ldcg(g_state + S_H3 + (p ^ 1) * NK + n * 128 + tid);
        s_e[tid] = -1e9f;
        __syncthreads();

        const int len = __ldg(x_lens + n);
        const int tc = min(len - t0, 512);
        const ulonglong2 h3v = ((const ulonglong2*)s_h3)[lane];

        // energy: warp w covers t-local [w*32, w*32+32), 2 t's in flight
        const int base = w * 32;
        const int lim = min(tc - base, 32);
        for (int it = 0; it < lim; it += 2) {
            const ulonglong2* kr1 = (const ulonglong2*)(key +
                ((size_t)(t0 + base + it) * N_DIM + n) * KS_DIM);
            ulonglong2 k1 = __ldcs(kr1 + lane);
            bool has2 = (it + 1 < lim);
            float e1, e2 = 0.f;
            e1 = f2sum(ffma2(k1.y, h3v.y, ffma2(k1.x, h3v.x, 0ULL)));
            if (has2) {
                const ulonglong2* kr2 = (const ulonglong2*)(key +
                    ((size_t)(t0 + base + it + 1) * N_DIM + n) * KS_DIM);
                ulonglong2 k2 = __ldcs(kr2 + lane);
                e2 = f2sum(ffma2(k2.y, h3v.y, ffma2(k2.x, h3v.x, 0ULL)));
            }
#pragma unroll
            for (int o = 16; o > 0; o >>= 1) {
                e1 += __shfl_xor_sync(0xffffffffu, e1, o);
                e2 += __shfl_xor_sync(0xffffffffu, e2, o);
            }
            if (lane == 0) {
                s_e[base + it] = e1;
                if (has2) s_e[base + it + 1] = e2;
            }
        }
        __syncthreads();

        // block max
        float m = s_e[tid];
        s_red[tid] = m; __syncthreads();
#pragma unroll
        for (int off = 256; off > 0; off >>= 1) {
            if (tid < off) s_red[tid] = fmaxf(s_red[tid], s_red[tid + off]);
            __syncthreads();
        }
        m = s_red[0];
        __syncthreads();

        float pv = (tid < tc) ? expf(s_e[tid] - m) : 0.f;
        s_e[tid] = pv;
        g_pw[n * T_DIM + t0 + tid] = pv;
        s_red[tid] = pv; __syncthreads();
#pragma unroll
        for (int off = 256; off > 0; off >>= 1) {
            if (tid < off) s_red[tid] += s_red[tid + off];
            __syncthreads();
        }
        if (tid == 0) { g_ms[n * 4 + s] = m; g_ls[n * 4 + s] = s_red[0]; }
        __syncthreads();

        // ctx partial: lane covers 16B of e-dim, tg = tid>>5 covers t strided 16
        {
            const int tg = tid >> 5;
            float4 acc = make_float4(0.f, 0.f, 0.f, 0.f);
            for (int t = tg; t < tc; t += 16) {
                float pt = s_e[t];
                float4 vv = __ldcs((const float4*)(values +
                    ((size_t)(t0 + t) * N_DIM + n) * VS_DIM) + lane);
                acc.x += pt * vv.x; acc.y += pt * vv.y;
                acc.z += pt * vv.z; acc.w += pt * vv.w;
            }
            red4[tid] = acc;
            __syncthreads();
#pragma unroll
            for (int off = 8; off > 0; off >>= 1) {
                if (tg < off) {
                    float4 o4 = red4[tid + off * 32];
                    float4 m4 = red4[tid];
                    m4.x += o4.x; m4.y += o4.y; m4.z += o4.z; m4.w += o4.w;
                    red4[tid] = m4;
                }
                __syncthreads();
            }
            if (tid < 32)
                ((float4*)(g_cw + (n * 4 + s) * 128))[tid] = red4[tid];
        }
    }
}

// -------- output (att + logits) for one batch row of step lo --------
__device__ void out_body(float* s_h3o, float* s_ctxo,
    const float* __restrict__ emb_W, const float* __restrict__ b_out,
    float* __restrict__ out, int lo, int h3slot, int n, int write_att, int tid)
{
    float sc[4];
    {
        float m0 = __ldcg(g_ms + n * 4 + 0), m1 = __ldcg(g_ms + n * 4 + 1);
        float m2 = __ldcg(g_ms + n * 4 + 2), m3 = __ldcg(g_ms + n * 4 + 3);
        float M = fmaxf(fmaxf(m0, m1), fmaxf(m2, m3));
        float e0 = expf(m0 - M), e1 = expf(m1 - M);
        float e2 = expf(m2 - M), e3 = expf(m3 - M);
        float Z = __ldcg(g_ls + n * 4 + 0) * e0 + __ldcg(g_ls + n * 4 + 1) * e1
                + __ldcg(g_ls + n * 4 + 2) * e2 + __ldcg(g_ls + n * 4 + 3) * e3;
        float iz = 1.f / Z;
        sc[0] = e0 * iz; sc[1] = e1 * iz; sc[2] = e2 * iz; sc[3] = e3 * iz;
    }
    if (write_att) {
        float* att = out + PRED_SIZE + ((size_t)n * L_DIM + lo) * T_DIM;
#pragma unroll
        for (int pass = 0; pass < 4; ++pass) {
            int t = pass * 512 + tid;
            att[t] = __ldcg(g_pw + n * T_DIM + t) * sc[t >> 9];
        }
    }
    if (tid < 128) {
        float cx = __ldcg(g_cw + (n * 4 + 0) * 128 + tid) * sc[0]
                 + __ldcg(g_cw + (n * 4 + 1) * 128 + tid) * sc[1]
                 + __ldcg(g_cw + (n * 4 + 2) * 128 + tid) * sc[2]
                 + __ldcg(g_cw + (n * 4 + 3) * 128 + tid) * sc[3];
        s_ctxo[tid] = cx;
        s_h3o[tid] = __ldcg(g_state + S_H3 + h3slot * NK + n * 128 + tid);
    }
    __syncthreads();
    const int w = tid >> 5, lane = tid & 31;
    for (int r = w; r < V_DIM; r += 16) {
        const float* er = emb_W + (size_t)r * E_DIM;
        float4 w1 = *(const float4*)(er + lane * 4);
        float4 w2 = *(const float4*)(er + 128 + lane * 4);
        float4 x1 = *(const float4*)(s_h3o + lane * 4);
        float4 x2 = *(const float4*)(s_ctxo + lane * 4);
        float sum = w1.x * x1.x + w1.y * x1.y + w1.z * x1.z + w1.w * x1.w
                  + w2.x * x2.x + w2.y * x2.y + w2.z * x2.z + w2.w * x2.w;
#pragma unroll
        for (int o = 16; o > 0; o >>= 1) sum += __shfl_xor_sync(0xffffffffu, sum, o);
        if (lane == 0) out[((size_t)n * L_DIM + lo) * V_DIM + r] = sum + b_out[r];
    }
    __syncthreads();
}

// ---------------- the persistent kernel ----------------
__global__ __launch_bounds__(512) void decoder_kernel(
    const float* __restrict__ key, const float* __restrict__ values,
    const int* __restrict__ x_lens,
    const float* __restrict__ emb_W,
    const float* __restrict__ Wih1, const float* __restrict__ Whh1,
    const float* __restrict__ Wih2, const float* __restrict__ Whh2,
    const float* __restrict__ bih2, const float* __restrict__ bhh2,
    const float* __restrict__ Wih3, const float* __restrict__ Whh3,
    const float* __restrict__ bih3, const float* __restrict__ bhh3,
    const float* __restrict__ b_out,
    float* __restrict__ out, int write_att)
{
    __shared__ __align__(16) char sbuf[32 * 65 * 16];  // x-slab / partials / s_e+red
    __shared__ float s_fin[4][4][64];
    __shared__ float s_scale[256];
    __shared__ __align__(16) float s_h3[128];
    __shared__ __align__(16) float s_ctx[128];

    const int bid = blockIdx.x;
    const int tid = threadIdx.x;
    const int nout = gridDim.x - 128;
    unsigned lsense = 0;

#pragma unroll 1
    for (int l = 0; l < L_DIM; ++l) {
        const int p = l & 1;
        // phase A: mm1 (blocks 0-127) || output of step l-1 (blocks 128+)
        if (bid < 128) {
            mm12_phase<1>(sbuf, s_fin, s_scale, Wih1, Whh1,
                          (const float*)0, (const float*)0, l, p, bid, tid);
        } else if (l > 0) {
            for (int n = bid - 128; n < N_DIM; n += nout)
                out_body(s_h3, s_ctx, emb_W, b_out, out, l - 1, p, n, write_att, tid);
        }
        gbar(lsense);
        if (bid < 128)
            mm12_phase<2>(sbuf, s_fin, s_scale, Wih2, Whh2, bih2, bhh2, l, p, bid, tid);
        gbar(lsense);
        if (bid < 128)
            mm3_phase(sbuf, Wih3, Whh3, bih3, bhh3, p, bid, tid);
        gbar(lsense);
        attn_phase(sbuf, s_h3, key, values, x_lens, p, bid, tid);
        gbar(lsense);
    }
    // epilogue: outputs for the final step
    if (bid < N_DIM)
        out_body(s_h3, s_ctx, emb_W, b_out, out, L_DIM - 1,
                 ((L_DIM - 1) & 1) ^ 1, bid, write_att, tid);
}

extern "C" void kernel_launch(void* const* d_in, const int* in_sizes, int n_in,
                              void* d_out, int out_size) {
    const float* key    = (const float*)d_in[0];
    const float* values = (const float*)d_in[1];
    const int*   x_lens = (const int*)d_in[2];
    const int*   text32 = (const int*)d_in[3];
    const float* emb_W  = (const float*)d_in[4];
    const float* Wih1 = (const float*)d_in[5];
    const float* Whh1 = (const float*)d_in[6];
    const float* bih1 = (const float*)d_in[7];
    const float* bhh1 = (const float*)d_in[8];
    const float* Wih2 = (const float*)d_in[9];
    const float* Whh2 = (const float*)d_in[10];
    const float* bih2 = (const float*)d_in[11];
    const float* bhh2 = (const float*)d_in[12];
    const float* Wih3 = (const float*)d_in[13];
    const float* Whh3 = (const float*)d_in[14];
    const float* bih3 = (const float*)d_in[15];
    const float* bhh3 = (const float*)d_in[16];
    const float* b_out = (const float*)d_in[17];
    float* out = (float*)d_out;

    int write_att = (out_size >= PRED_SIZE + ATT_SIZE) ? 1 : 0;

    int dev = 0, nsm = 148;
    cudaGetDevice(&dev);
    cudaDeviceGetAttribute(&nsm, cudaDevAttrMultiProcessorCount, dev);
    if (nsm < 148) nsm = 148;  // need >=128 mm blocks + output blocks, all co-resident

    zero_kernel<<<216, 256>>>();
    detect_kernel<<<(N_DIM * L_DIM / 2 + 255) / 256, 256>>>(text32);
    decode_kernel<<<(N_DIM * L_DIM + 255) / 256, 256>>>(text32);
    emb_kernel<<<dim3(8, V_DIM), 256>>>(emb_W, Wih1, bih1, bhh1);

    decoder_kernel<<<nsm, 512>>>(key, values, x_lens, emb_W,
                                 Wih1, Whh1, Wih2, Whh2, bih2, bhh2,
                                 Wih3, Whh3, bih3, bhh3, b_out,
                                 out, write_att);
}